// round 1
// baseline (speedup 1.0000x reference)
#include <cuda_runtime.h>
#include <math.h>

#define BB   256
#define HH   32
#define WW   32
#define AA   5
#define NCC  20
#define MM   50
#define NCELLS (BB*HH*WW)

// Scratch (no device allocation allowed): target values + min-class-per-cell.
__device__ float4 g_tvals[NCELLS];   // xo, yo, tw, th (last valid object wins)
__device__ int    g_cls[NCELLS];     // -1 = no object; else min class index in cell

__global__ void clear_kernel(float* __restrict__ dout) {
    int i = blockIdx.x * blockDim.x + threadIdx.x;
    if (i < NCELLS) g_cls[i] = -1;
    if (i < 4) dout[i] = 0.0f;
}

// One thread per batch; serial loop over objects reproduces the reference's
// sequential scatter semantics exactly (last write wins for box vals,
// argmax-of-onehot == min class index among colliding objects).
__global__ void build_kernel(const float4* __restrict__ gt_boxes,
                             const int* __restrict__ gt_classes,
                             const int* __restrict__ num_box) {
    int b = blockIdx.x * blockDim.x + threadIdx.x;
    if (b >= BB) return;
    int nb = num_box[b];
    if (nb > MM) nb = MM;
    for (int m = 0; m < nb; m++) {
        float4 box = gt_boxes[b * MM + m];
        float x = box.x * (float)HH;
        float y = box.y * (float)HH;
        int gx = (int)floorf(x);
        int gy = (int)floorf(y);
        int cell = b * (HH * WW) + gy * WW + gx;
        g_tvals[cell] = make_float4(x - (float)gx, y - (float)gy,
                                    box.z * (float)HH, box.w * (float)HH);
        int c = gt_classes[b * MM + m];
        int old = g_cls[cell];
        g_cls[cell] = (old < 0 || c < old) ? c : old;
    }
}

__device__ __forceinline__ float sigm(float x) { return 1.0f / (1.0f + expf(-x)); }

__global__ void __launch_bounds__(256)
loss_kernel(const float* __restrict__ out,
            const float* __restrict__ anchor,
            float* __restrict__ dout) {
    int n  = blockIdx.x * blockDim.x + threadIdx.x;   // cell id in [0, NCELLS)
    int hw = n & (HH * WW - 1);
    int b  = n >> 10;
    int wq = hw & (WW - 1);
    int hq = hw >> 5;

    const float* base = out + (size_t)b * (AA * (5 + NCC)) * (HH * WW) + hw;

    float pc[AA];
    float noobj = 0.0f, boxl = 0.0f, confl = 0.0f, clsl = 0.0f;

    // Confidence channels: needed for every cell (noobj term).
    #pragma unroll
    for (int a = 0; a < AA; a++) {
        float l = base[(a * 25 + NCC) * 1024];
        pc[a] = sigm(l);
        noobj += pc[a] * pc[a];
    }

    int cls = g_cls[n];
    if (cls >= 0) {
        float4 tv = g_tvals[n];
        float tx = (float)wq + tv.x;
        float ty = (float)hq + tv.y;
        float tw = tv.z, th = tv.w;
        float tx1 = tx - tw * 0.5f, ty1 = ty - th * 0.5f;
        float tx2 = tx + tw * 0.5f, ty2 = ty + th * 0.5f;
        float tarea = tw * th;

        float best_iou = -1.0f;
        int best = 0;
        float bx = 0, by = 0, bw = 0, bh = 0;
        #pragma unroll
        for (int a = 0; a < AA; a++) {
            float sx = sigm(base[(a * 25 + NCC + 1) * 1024]);
            float sy = sigm(base[(a * 25 + NCC + 2) * 1024]);
            float pw = expf(base[(a * 25 + NCC + 3) * 1024]) * anchor[a * 2 + 0];
            float ph = expf(base[(a * 25 + NCC + 4) * 1024]) * anchor[a * 2 + 1];
            float px = (float)wq + sx;
            float py = (float)hq + sy;
            float ax1 = px - pw * 0.5f, ay1 = py - ph * 0.5f;
            float ax2 = px + pw * 0.5f, ay2 = py + ph * 0.5f;
            float iw = fmaxf(fminf(ax2, tx2) - fmaxf(ax1, tx1), 0.0f);
            float ih = fmaxf(fminf(ay2, ty2) - fmaxf(ay1, ty1), 0.0f);
            float inter = iw * ih;
            float uni = pw * ph + tarea - inter;
            float iou = inter / fmaxf(uni, 1e-10f);
            if (iou > best_iou) {   // strict > : first max wins (matches jnp.argmax)
                best_iou = iou; best = a;
                bx = px; by = py; bw = pw; bh = ph;
            }
        }

        float d0 = bx - tx;
        float d1 = by - ty;
        float d2 = sqrtf(bw) - sqrtf(tw);
        float d3 = sqrtf(bh) - sqrtf(th);
        boxl = d0 * d0 + d1 * d1 + d2 * d2 + d3 * d3;

        float pcb = pc[best];
        confl = (pcb - 1.0f) * (pcb - 1.0f);
        noobj -= pcb * pcb;   // mask removes best anchor from noobj term

        // Cross-entropy over the 20 class logits of the best anchor.
        const float* cb = base + (size_t)best * 25 * 1024;
        float l[NCC];
        float mx = -1e30f;
        #pragma unroll
        for (int c = 0; c < NCC; c++) {
            l[c] = cb[c * 1024];
            mx = fmaxf(mx, l[c]);
        }
        float s = 0.0f;
        #pragma unroll
        for (int c = 0; c < NCC; c++) s += expf(l[c] - mx);
        clsl = mx + logf(s) - l[cls];
    }

    // Block reduction: warp shuffle, then shared across warps.
    #pragma unroll
    for (int off = 16; off > 0; off >>= 1) {
        boxl  += __shfl_down_sync(0xffffffffu, boxl,  off);
        confl += __shfl_down_sync(0xffffffffu, confl, off);
        noobj += __shfl_down_sync(0xffffffffu, noobj, off);
        clsl  += __shfl_down_sync(0xffffffffu, clsl,  off);
    }
    __shared__ float sm[4][8];
    int lane = threadIdx.x & 31;
    int wid  = threadIdx.x >> 5;
    if (lane == 0) {
        sm[0][wid] = boxl; sm[1][wid] = confl;
        sm[2][wid] = noobj; sm[3][wid] = clsl;
    }
    __syncthreads();
    if (threadIdx.x == 0) {
        float s0 = 0, s1 = 0, s2 = 0, s3 = 0;
        #pragma unroll
        for (int i = 0; i < 8; i++) {
            s0 += sm[0][i]; s1 += sm[1][i]; s2 += sm[2][i]; s3 += sm[3][i];
        }
        atomicAdd(&dout[0], s0 * (5.0f  / 256.0f));   // LAM_COORD / B
        atomicAdd(&dout[1], s1 * (1.0f  / 256.0f));   // LAM_OBJ / B
        atomicAdd(&dout[2], s2 * (0.5f  / 256.0f));   // LAM_NOOBJ / B
        atomicAdd(&dout[3], s3 * (1.0f  / 256.0f));   // LAM_CLS / B
    }
}

extern "C" void kernel_launch(void* const* d_in, const int* in_sizes, int n_in,
                              void* d_out, int out_size) {
    const float*  out_t      = (const float*)d_in[0];
    const float4* gt_boxes   = (const float4*)d_in[1];
    const float*  anchor     = (const float*)d_in[2];
    const int*    gt_classes = (const int*)d_in[3];
    const int*    num_box    = (const int*)d_in[4];
    float* dout = (float*)d_out;

    clear_kernel<<<NCELLS / 256, 256>>>(dout);
    build_kernel<<<1, 256>>>(gt_boxes, gt_classes, num_box);
    loss_kernel<<<NCELLS / 256, 256>>>(out_t, anchor, dout);
}

// round 2
// speedup vs baseline: 1.6116x; 1.6116x over previous
#include <cuda_runtime.h>
#include <math.h>

#define BB   256
#define HH   32
#define WW   32
#define AA   5
#define NCC  20
#define MM   50
#define NCELLS (BB*HH*WW)

// Zero-initialized at module load; loss_kernel restores consumed entries to 0,
// so every launch (correctness run + each graph replay) sees a clean state.
__device__ int g_win[NCELLS];   // 0 = empty, else (m+1); atomicMax => last object wins
__device__ int g_cle[NCELLS];   // 0 = empty, else (64-cls); atomicMax => min class wins

__global__ void build_kernel(const float4* __restrict__ gt_boxes,
                             const int* __restrict__ gt_classes,
                             const int* __restrict__ num_box,
                             float* __restrict__ dout) {
    int i = blockIdx.x * blockDim.x + threadIdx.x;   // object id in [0, BB*MM)
    if (i < 4) dout[i] = 0.0f;
    if (i >= BB * MM) return;
    int b = i / MM;
    int m = i - b * MM;
    if (m >= num_box[b]) return;
    float4 box = gt_boxes[i];
    int gx = (int)floorf(box.x * (float)HH);
    int gy = (int)floorf(box.y * (float)HH);
    int cell = b * (HH * WW) + gy * WW + gx;
    atomicMax(&g_win[cell], m + 1);
    atomicMax(&g_cle[cell], 64 - gt_classes[i]);
}

__device__ __forceinline__ float sigm(float x) { return 1.0f / (1.0f + expf(-x)); }

// One thread = 4 consecutive cells (float4 conf loads, int4 winner loads).
__global__ void __launch_bounds__(256)
loss_kernel(const float* __restrict__ out,
            const float4* __restrict__ gt_boxes,
            const float* __restrict__ anchor,
            float* __restrict__ dout) {
    int t   = blockIdx.x * blockDim.x + threadIdx.x;  // [0, NCELLS/4)
    int n0  = t * 4;
    int b   = n0 >> 10;
    int hw0 = n0 & (HH * WW - 1);

    const float* base = out + (size_t)b * (AA * (5 + NCC)) * (HH * WW) + hw0;

    // Confidence logits for 5 anchors x 4 cells (fully coalesced 16B loads).
    float4 cl[AA];
    #pragma unroll
    for (int a = 0; a < AA; a++)
        cl[a] = *(const float4*)(base + (a * 25 + NCC) * 1024);

    int4 winv = *(const int4*)&g_win[n0];

    float noobj = 0.0f, boxl = 0.0f, confl = 0.0f, clsl = 0.0f;

    #pragma unroll
    for (int j = 0; j < 4; j++) {
        float pc[AA];
        #pragma unroll
        for (int a = 0; a < AA; a++) {
            float v = (j == 0) ? cl[a].x : (j == 1) ? cl[a].y : (j == 2) ? cl[a].z : cl[a].w;
            pc[a] = sigm(v);
            noobj += pc[a] * pc[a];
        }

        int w = (j == 0) ? winv.x : (j == 1) ? winv.y : (j == 2) ? winv.z : winv.w;
        if (w) {
            int n  = n0 + j;
            int hw = hw0 + j;
            int wq = hw & (WW - 1);
            int hq = hw >> 5;

            // Recompute target from the winning object (tx = x*32 exactly).
            float4 box = gt_boxes[b * MM + (w - 1)];
            float tx = box.x * (float)HH;
            float ty = box.y * (float)HH;
            float tw = box.z * (float)HH;
            float th = box.w * (float)HH;
            float tx1 = tx - tw * 0.5f, ty1 = ty - th * 0.5f;
            float tx2 = tx + tw * 0.5f, ty2 = ty + th * 0.5f;
            float tarea = tw * th;

            float best_iou = -1.0f;
            int   best = 0;
            float bx = 0, by = 0, bw = 0, bh = 0;
            const float* cellb = base + j;
            #pragma unroll
            for (int a = 0; a < AA; a++) {
                float sx = sigm(cellb[(a * 25 + NCC + 1) * 1024]);
                float sy = sigm(cellb[(a * 25 + NCC + 2) * 1024]);
                float pw = expf(cellb[(a * 25 + NCC + 3) * 1024]) * anchor[a * 2 + 0];
                float ph = expf(cellb[(a * 25 + NCC + 4) * 1024]) * anchor[a * 2 + 1];
                float px = (float)wq + sx;
                float py = (float)hq + sy;
                float ax1 = px - pw * 0.5f, ay1 = py - ph * 0.5f;
                float ax2 = px + pw * 0.5f, ay2 = py + ph * 0.5f;
                float iw = fmaxf(fminf(ax2, tx2) - fmaxf(ax1, tx1), 0.0f);
                float ih = fmaxf(fminf(ay2, ty2) - fmaxf(ay1, ty1), 0.0f);
                float inter = iw * ih;
                float uni = pw * ph + tarea - inter;
                float iou = inter / fmaxf(uni, 1e-10f);
                if (iou > best_iou) {   // strict > : first max wins (jnp.argmax)
                    best_iou = iou; best = a;
                    bx = px; by = py; bw = pw; bh = ph;
                }
            }

            float d0 = bx - tx;
            float d1 = by - ty;
            float d2 = sqrtf(bw) - sqrtf(tw);
            float d3 = sqrtf(bh) - sqrtf(th);
            boxl += d0 * d0 + d1 * d1 + d2 * d2 + d3 * d3;

            // Track pc[best] without dynamic register indexing.
            float pcb = pc[0];
            #pragma unroll
            for (int a = 1; a < AA; a++) pcb = (best == a) ? pc[a] : pcb;
            confl += (pcb - 1.0f) * (pcb - 1.0f);
            noobj -= pcb * pcb;

            // Cross-entropy over the best anchor's 20 class logits.
            int cls = 64 - g_cle[n];
            const float* cb = cellb + (size_t)best * 25 * 1024;
            float mx = -1e30f, lc = 0.0f;
            float l[NCC];
            #pragma unroll
            for (int c = 0; c < NCC; c++) {
                l[c] = cb[c * 1024];
                mx = fmaxf(mx, l[c]);
                lc = (c == cls) ? l[c] : lc;
            }
            float s = 0.0f;
            #pragma unroll
            for (int c = 0; c < NCC; c++) s += expf(l[c] - mx);
            clsl += mx + logf(s) - lc;

            // Self-clean for the next launch/replay.
            g_win[n] = 0;
            g_cle[n] = 0;
        }
    }

    #pragma unroll
    for (int off = 16; off > 0; off >>= 1) {
        boxl  += __shfl_down_sync(0xffffffffu, boxl,  off);
        confl += __shfl_down_sync(0xffffffffu, confl, off);
        noobj += __shfl_down_sync(0xffffffffu, noobj, off);
        clsl  += __shfl_down_sync(0xffffffffu, clsl,  off);
    }
    __shared__ float sm[4][8];
    int lane = threadIdx.x & 31;
    int wid  = threadIdx.x >> 5;
    if (lane == 0) {
        sm[0][wid] = boxl; sm[1][wid] = confl;
        sm[2][wid] = noobj; sm[3][wid] = clsl;
    }
    __syncthreads();
    if (threadIdx.x == 0) {
        float s0 = 0, s1 = 0, s2 = 0, s3 = 0;
        #pragma unroll
        for (int i = 0; i < 8; i++) {
            s0 += sm[0][i]; s1 += sm[1][i]; s2 += sm[2][i]; s3 += sm[3][i];
        }
        atomicAdd(&dout[0], s0 * (5.0f / 256.0f));   // LAM_COORD / B
        atomicAdd(&dout[1], s1 * (1.0f / 256.0f));   // LAM_OBJ  / B
        atomicAdd(&dout[2], s2 * (0.5f / 256.0f));   // LAM_NOOBJ/ B
        atomicAdd(&dout[3], s3 * (1.0f / 256.0f));   // LAM_CLS  / B
    }
}

extern "C" void kernel_launch(void* const* d_in, const int* in_sizes, int n_in,
                              void* d_out, int out_size) {
    const float*  out_t      = (const float*)d_in[0];
    const float4* gt_boxes   = (const float4*)d_in[1];
    const float*  anchor     = (const float*)d_in[2];
    const int*    gt_classes = (const int*)d_in[3];
    const int*    num_box    = (const int*)d_in[4];
    float* dout = (float*)d_out;

    build_kernel<<<(BB * MM + 255) / 256, 256>>>((const float4*)gt_boxes,
                                                 gt_classes, num_box, dout);
    loss_kernel<<<NCELLS / 4 / 256, 256>>>(out_t, (const float4*)gt_boxes,
                                           anchor, dout);
}

// round 3
// speedup vs baseline: 2.4591x; 1.5259x over previous
#include <cuda_runtime.h>
#include <math.h>

#define BB   256
#define HH   32
#define WW   32
#define AA   5
#define NCC  20
#define MM   50
#define NCELLS (BB*HH*WW)

#define DENSE_BLOCKS 1280              // 256*5*256 float4 / 256 threads
#define SPARSE_BLOCKS 50               // 12800 objects / 256
#define NOBJ (BB*MM)

// Zero at module load; winner threads restore consumed entries to 0 each launch.
__device__ int g_win[NCELLS];   // 0 = empty, else (m+1); atomicMax => last object wins
__device__ int g_cle[NCELLS];   // 0 = empty, else (64-cls); atomicMax => min class wins

__global__ void build_kernel(const float4* __restrict__ gt_boxes,
                             const int* __restrict__ gt_classes,
                             const int* __restrict__ num_box,
                             float* __restrict__ dout) {
    int i = blockIdx.x * blockDim.x + threadIdx.x;
    if (i < 4) dout[i] = 0.0f;
    if (i >= NOBJ) return;
    int b = i / MM;
    int m = i - b * MM;
    if (m >= num_box[b]) return;
    float4 box = gt_boxes[i];
    int gx = (int)floorf(box.x * (float)HH);
    int gy = (int)floorf(box.y * (float)HH);
    int cell = b * (HH * WW) + gy * WW + gx;
    atomicMax(&g_win[cell], m + 1);
    atomicMax(&g_cle[cell], 64 - gt_classes[i]);
}

__device__ __forceinline__ float sigm(float x) { return 1.0f / (1.0f + __expf(-x)); }

__global__ void __launch_bounds__(256)
fused_loss_kernel(const float* __restrict__ out,
                  const float4* __restrict__ gt_boxes,
                  const float* __restrict__ anchor,
                  const int* __restrict__ num_box,
                  float* __restrict__ dout) {
    float boxl = 0.0f, confl = 0.0f, noobj = 0.0f, clsl = 0.0f;

    if (blockIdx.x < DENSE_BLOCKS) {
        // ---- dense: sum sigm(conf)^2 over every conf channel value ----
        int t = blockIdx.x * 256 + threadIdx.x;      // [0, 327680) float4 ids
        int b = t / 1280;                            // 5*256 float4 per batch
        int r = t - b * 1280;
        int a = r >> 8;
        int q = r & 255;
        const float4* p = (const float4*)out + (size_t)(b * 125 + a * 25 + NCC) * 256 + q;
        float4 v = *p;
        float s0 = sigm(v.x), s1 = sigm(v.y), s2 = sigm(v.z), s3 = sigm(v.w);
        noobj = s0 * s0 + s1 * s1 + s2 * s2 + s3 * s3;
    } else {
        // ---- sparse: one thread per GT object; only the cell winner works ----
        int i = (blockIdx.x - DENSE_BLOCKS) * 256 + threadIdx.x;
        if (i < NOBJ) {
            int b = i / MM;
            int m = i - b * MM;
            if (m < num_box[b]) {
                float4 box = gt_boxes[i];
                float tx = box.x * (float)HH;
                float ty = box.y * (float)HH;
                int wq = (int)floorf(tx);
                int hq = (int)floorf(ty);
                int cell = b * (HH * WW) + hq * WW + wq;
                if (g_win[cell] == m + 1) {
                    int cls = 64 - g_cle[cell];
                    g_win[cell] = 0;          // self-clean for next launch/replay
                    g_cle[cell] = 0;

                    int hw = cell & (HH * WW - 1);
                    const float* cellb = out + (size_t)b * 125 * 1024 + hw;

                    float tw = box.z * (float)HH;
                    float th = box.w * (float)HH;
                    float tx1 = tx - tw * 0.5f, ty1 = ty - th * 0.5f;
                    float tx2 = tx + tw * 0.5f, ty2 = ty + th * 0.5f;
                    float tarea = tw * th;

                    float best_iou = -1.0f;
                    int   best = 0;
                    float bx = 0, by = 0, bw = 0, bh = 0, pcb = 0;
                    #pragma unroll
                    for (int a = 0; a < AA; a++) {
                        const float* ab = cellb + a * 25 * 1024;
                        float pconf = sigm(ab[NCC * 1024]);
                        float sx = sigm(ab[(NCC + 1) * 1024]);
                        float sy = sigm(ab[(NCC + 2) * 1024]);
                        float pw = __expf(ab[(NCC + 3) * 1024]) * anchor[a * 2 + 0];
                        float ph = __expf(ab[(NCC + 4) * 1024]) * anchor[a * 2 + 1];
                        float px = (float)wq + sx;
                        float py = (float)hq + sy;
                        float ax1 = px - pw * 0.5f, ay1 = py - ph * 0.5f;
                        float ax2 = px + pw * 0.5f, ay2 = py + ph * 0.5f;
                        float iw = fmaxf(fminf(ax2, tx2) - fmaxf(ax1, tx1), 0.0f);
                        float ih = fmaxf(fminf(ay2, ty2) - fmaxf(ay1, ty1), 0.0f);
                        float inter = iw * ih;
                        float uni = pw * ph + tarea - inter;
                        float iou = inter / fmaxf(uni, 1e-10f);
                        if (iou > best_iou) {   // strict >: first max wins (jnp.argmax)
                            best_iou = iou; best = a;
                            bx = px; by = py; bw = pw; bh = ph; pcb = pconf;
                        }
                    }

                    float d0 = bx - tx;
                    float d1 = by - ty;
                    float d2 = sqrtf(bw) - sqrtf(tw);
                    float d3 = sqrtf(bh) - sqrtf(th);
                    boxl = d0 * d0 + d1 * d1 + d2 * d2 + d3 * d3;

                    confl = (pcb - 1.0f) * (pcb - 1.0f);
                    noobj = -pcb * pcb;       // remove best anchor from noobj sum

                    const float* cb = cellb + (size_t)best * 25 * 1024;
                    float mx = -1e30f, lc = 0.0f;
                    float l[NCC];
                    #pragma unroll
                    for (int c = 0; c < NCC; c++) {
                        l[c] = cb[c * 1024];
                        mx = fmaxf(mx, l[c]);
                        lc = (c == cls) ? l[c] : lc;
                    }
                    float s = 0.0f;
                    #pragma unroll
                    for (int c = 0; c < NCC; c++) s += __expf(l[c] - mx);
                    clsl = mx + __logf(s) - lc;
                }
            }
        }
    }

    // ---- block reduction (all threads reach here) ----
    #pragma unroll
    for (int off = 16; off > 0; off >>= 1) {
        boxl  += __shfl_down_sync(0xffffffffu, boxl,  off);
        confl += __shfl_down_sync(0xffffffffu, confl, off);
        noobj += __shfl_down_sync(0xffffffffu, noobj, off);
        clsl  += __shfl_down_sync(0xffffffffu, clsl,  off);
    }
    __shared__ float sm[4][8];
    int lane = threadIdx.x & 31;
    int wid  = threadIdx.x >> 5;
    if (lane == 0) {
        sm[0][wid] = boxl; sm[1][wid] = confl;
        sm[2][wid] = noobj; sm[3][wid] = clsl;
    }
    __syncthreads();
    if (threadIdx.x == 0) {
        float s0 = 0, s1 = 0, s2 = 0, s3 = 0;
        #pragma unroll
        for (int i = 0; i < 8; i++) {
            s0 += sm[0][i]; s1 += sm[1][i]; s2 += sm[2][i]; s3 += sm[3][i];
        }
        if (s0 != 0.0f) atomicAdd(&dout[0], s0 * (5.0f / 256.0f));   // LAM_COORD/B
        if (s1 != 0.0f) atomicAdd(&dout[1], s1 * (1.0f / 256.0f));   // LAM_OBJ/B
        if (s2 != 0.0f) atomicAdd(&dout[2], s2 * (0.5f / 256.0f));   // LAM_NOOBJ/B
        if (s3 != 0.0f) atomicAdd(&dout[3], s3 * (1.0f / 256.0f));   // LAM_CLS/B
    }
}

extern "C" void kernel_launch(void* const* d_in, const int* in_sizes, int n_in,
                              void* d_out, int out_size) {
    const float*  out_t      = (const float*)d_in[0];
    const float4* gt_boxes   = (const float4*)d_in[1];
    const float*  anchor     = (const float*)d_in[2];
    const int*    gt_classes = (const int*)d_in[3];
    const int*    num_box    = (const int*)d_in[4];
    float* dout = (float*)d_out;

    build_kernel<<<(NOBJ + 255) / 256, 256>>>(gt_boxes, gt_classes, num_box, dout);
    fused_loss_kernel<<<DENSE_BLOCKS + SPARSE_BLOCKS, 256>>>(
        out_t, gt_boxes, anchor, num_box, dout);
}

// round 4
// speedup vs baseline: 2.7951x; 1.1366x over previous
#include <cuda_runtime.h>
#include <math.h>

#define BB   256
#define HH   32
#define WW   32
#define AA   5
#define NCC  20
#define MM   50
#define NOBJ (BB*MM)

#define SPARSE_BLOCKS 50               // 12800 objects / 256
#define DENSE_BLOCKS  640              // 327680 conf-float4 / (256 thr * 2)
#define TOTAL_BLOCKS  (SPARSE_BLOCKS + DENSE_BLOCKS)
#define NF4           (BB*AA*256)      // 327680 conf float4s
#define HALF_F4       (NF4/2)          // 163840

// Zero-init at load; last block resets them each launch -> replay-safe.
__device__ float    g_acc[4];
__device__ unsigned g_cnt;

__device__ __forceinline__ float sigm(float x) { return 1.0f / (1.0f + __expf(-x)); }

// linear conf-float4 id -> pointer into out
__device__ __forceinline__ const float4* conf_ptr(const float* out, int t) {
    int b = t / (AA * 256);
    int r = t - b * (AA * 256);
    int a = r >> 8;
    int q = r & 255;
    return (const float4*)out + (size_t)(b * 125 + a * 25 + NCC) * 256 + q;
}

__global__ void __launch_bounds__(256)
fused_loss_kernel(const float* __restrict__ out,
                  const float4* __restrict__ gt_boxes,
                  const float* __restrict__ anchor,
                  const int* __restrict__ gt_classes,
                  const int* __restrict__ num_box,
                  float* __restrict__ dout) {
    float boxl = 0.0f, confl = 0.0f, noobj = 0.0f, clsl = 0.0f;

    if (blockIdx.x >= SPARSE_BLOCKS) {
        // ---- dense: sum sigm(conf)^2; 2 coalesced float4 per thread ----
        int t = (blockIdx.x - SPARSE_BLOCKS) * 256 + threadIdx.x;  // [0, HALF_F4)
        float4 v0 = *conf_ptr(out, t);
        float4 v1 = *conf_ptr(out, t + HALF_F4);
        float s;
        s = sigm(v0.x); noobj += s * s;
        s = sigm(v0.y); noobj += s * s;
        s = sigm(v0.z); noobj += s * s;
        s = sigm(v0.w); noobj += s * s;
        s = sigm(v1.x); noobj += s * s;
        s = sigm(v1.y); noobj += s * s;
        s = sigm(v1.z); noobj += s * s;
        s = sigm(v1.w); noobj += s * s;
    } else {
        // ---- sparse: one thread per GT object; self-determined winner ----
        int i = blockIdx.x * 256 + threadIdx.x;     // [0, NOBJ)
        int b = i / MM;
        int m = i - b * MM;
        int nb = num_box[b];
        if (nb > MM) nb = MM;
        if (m < nb) {
            float4 box = gt_boxes[i];
            float tx = box.x * (float)HH;
            float ty = box.y * (float)HH;
            int wq = (int)floorf(tx);
            int hq = (int)floorf(ty);
            int mycell = hq * WW + wq;

            // Scan this batch's valid objects: winner = max m in my cell,
            // class = min among colliders (argmax-of-onehot semantics).
            int last = -1, minc = 1 << 30;
            const float4* row = gt_boxes + b * MM;
            for (int m2 = 0; m2 < nb; m2++) {
                float4 b2 = row[m2];
                int c2 = ((int)floorf(b2.y * (float)HH)) * WW
                       +  (int)floorf(b2.x * (float)HH);
                if (c2 == mycell) {
                    last = m2;
                    int cc = gt_classes[b * MM + m2];
                    minc = (cc < minc) ? cc : minc;
                }
            }

            if (last == m) {             // this thread owns the cell
                int cls = minc;
                const float* cellb = out + (size_t)b * 125 * 1024 + mycell;

                float tw = box.z * (float)HH;
                float th = box.w * (float)HH;
                float tx1 = tx - tw * 0.5f, ty1 = ty - th * 0.5f;
                float tx2 = tx + tw * 0.5f, ty2 = ty + th * 0.5f;
                float tarea = tw * th;

                float best_iou = -1.0f;
                int   best = 0;
                float bx = 0, by = 0, bw = 0, bh = 0, pcb = 0;
                #pragma unroll
                for (int a = 0; a < AA; a++) {
                    const float* ab = cellb + a * 25 * 1024;
                    float pconf = sigm(ab[NCC * 1024]);
                    float sx = sigm(ab[(NCC + 1) * 1024]);
                    float sy = sigm(ab[(NCC + 2) * 1024]);
                    float pw = __expf(ab[(NCC + 3) * 1024]) * anchor[a * 2 + 0];
                    float ph = __expf(ab[(NCC + 4) * 1024]) * anchor[a * 2 + 1];
                    float px = (float)wq + sx;
                    float py = (float)hq + sy;
                    float ax1 = px - pw * 0.5f, ay1 = py - ph * 0.5f;
                    float ax2 = px + pw * 0.5f, ay2 = py + ph * 0.5f;
                    float iw = fmaxf(fminf(ax2, tx2) - fmaxf(ax1, tx1), 0.0f);
                    float ih = fmaxf(fminf(ay2, ty2) - fmaxf(ay1, ty1), 0.0f);
                    float inter = iw * ih;
                    float uni = pw * ph + tarea - inter;
                    float iou = inter / fmaxf(uni, 1e-10f);
                    if (iou > best_iou) {   // strict >: first max wins (jnp.argmax)
                        best_iou = iou; best = a;
                        bx = px; by = py; bw = pw; bh = ph; pcb = pconf;
                    }
                }

                float d0 = bx - tx;
                float d1 = by - ty;
                float d2 = sqrtf(bw) - sqrtf(tw);
                float d3 = sqrtf(bh) - sqrtf(th);
                boxl = d0 * d0 + d1 * d1 + d2 * d2 + d3 * d3;

                confl = (pcb - 1.0f) * (pcb - 1.0f);
                noobj = -pcb * pcb;        // remove best anchor from noobj sum

                const float* cb = cellb + (size_t)best * 25 * 1024;
                float mx = -1e30f, lc = 0.0f;
                float l[NCC];
                #pragma unroll
                for (int c = 0; c < NCC; c++) {
                    l[c] = cb[c * 1024];
                    mx = fmaxf(mx, l[c]);
                    lc = (c == cls) ? l[c] : lc;
                }
                float sum = 0.0f;
                #pragma unroll
                for (int c = 0; c < NCC; c++) sum += __expf(l[c] - mx);
                clsl = mx + __logf(sum) - lc;
            }
        }
    }

    // ---- block reduction ----
    #pragma unroll
    for (int off = 16; off > 0; off >>= 1) {
        boxl  += __shfl_down_sync(0xffffffffu, boxl,  off);
        confl += __shfl_down_sync(0xffffffffu, confl, off);
        noobj += __shfl_down_sync(0xffffffffu, noobj, off);
        clsl  += __shfl_down_sync(0xffffffffu, clsl,  off);
    }
    __shared__ float sm[4][8];
    int lane = threadIdx.x & 31;
    int wid  = threadIdx.x >> 5;
    if (lane == 0) {
        sm[0][wid] = boxl; sm[1][wid] = confl;
        sm[2][wid] = noobj; sm[3][wid] = clsl;
    }
    __syncthreads();
    if (threadIdx.x == 0) {
        float s0 = 0, s1 = 0, s2 = 0, s3 = 0;
        #pragma unroll
        for (int k = 0; k < 8; k++) {
            s0 += sm[0][k]; s1 += sm[1][k]; s2 += sm[2][k]; s3 += sm[3][k];
        }
        if (s0 != 0.0f) atomicAdd(&g_acc[0], s0);
        if (s1 != 0.0f) atomicAdd(&g_acc[1], s1);
        if (s2 != 0.0f) atomicAdd(&g_acc[2], s2);
        if (s3 != 0.0f) atomicAdd(&g_acc[3], s3);
        __threadfence();
        unsigned old = atomicInc(&g_cnt, TOTAL_BLOCKS - 1);
        if (old == TOTAL_BLOCKS - 1) {          // last block finalizes
            volatile float* a = g_acc;
            dout[0] = a[0] * (5.0f / 256.0f);   // LAM_COORD / B
            dout[1] = a[1] * (1.0f / 256.0f);   // LAM_OBJ   / B
            dout[2] = a[2] * (0.5f / 256.0f);   // LAM_NOOBJ / B
            dout[3] = a[3] * (1.0f / 256.0f);   // LAM_CLS   / B
            g_acc[0] = 0.0f; g_acc[1] = 0.0f;   // reset for next replay
            g_acc[2] = 0.0f; g_acc[3] = 0.0f;
        }
    }
}

extern "C" void kernel_launch(void* const* d_in, const int* in_sizes, int n_in,
                              void* d_out, int out_size) {
    const float*  out_t      = (const float*)d_in[0];
    const float4* gt_boxes   = (const float4*)d_in[1];
    const float*  anchor     = (const float*)d_in[2];
    const int*    gt_classes = (const int*)d_in[3];
    const int*    num_box    = (const int*)d_in[4];
    float* dout = (float*)d_out;

    fused_loss_kernel<<<TOTAL_BLOCKS, 256>>>(out_t, gt_boxes, anchor,
                                             gt_classes, num_box, dout);
}